// round 10
// baseline (speedup 1.0000x reference)
#include <cuda_runtime.h>
#include <cstdint>

#define BATCH   256
#define TSTEPS  1000
#define LIN     30
#define KW      7
#define LO      24
#define JDIM    384
#define NOUT    35
#define NTHREADS 448     // warps 0-11: A+B | w12: B-extra + C32-34 + cp(b0) | w13: C + B-tail + cp(b1)
#define CHUNK   50
#define NCHUNK  (TSTEPS / CHUNK)
#define ROWP    32       // padded x row stride (floats)
#define SPKG    36       // padded spike group stride (floats)
#define PCOL    36

typedef unsigned long long ull;

__device__ __forceinline__ uint32_t smem_u32(const void* p) {
    return (uint32_t)__cvta_generic_to_shared(p);
}
__device__ __forceinline__ void cp_async8(uint32_t dst, const void* src) {
    asm volatile("cp.async.ca.shared.global [%0], [%1], 8;" :: "r"(dst), "l"(src));
}
__device__ __forceinline__ void cp_commit() { asm volatile("cp.async.commit_group;"); }
__device__ __forceinline__ void cp_wait1()  { asm volatile("cp.async.wait_group 1;" ::: "memory"); }
__device__ __forceinline__ void cp_wait0()  { asm volatile("cp.async.wait_group 0;" ::: "memory"); }

__device__ __forceinline__ ull pk(float a, float b) {
    ull r; asm("mov.b64 %0, {%1,%2};" : "=l"(r) : "f"(a), "f"(b)); return r;
}
__device__ __forceinline__ void upk(ull v, float& a, float& b) {
    asm("mov.b64 {%0,%1}, %2;" : "=f"(a), "=f"(b) : "l"(v));
}
__device__ __forceinline__ ull f2fma(ull a, ull b, ull c) {
    ull d; asm("fma.rn.f32x2 %0, %1, %2, %3;" : "=l"(d) : "l"(a), "l"(b), "l"(c)); return d;
}

#define PARSTR (12 * SPKG * 4)            // spk parity stride (bytes)
#define BATSTR (2 * 12 * SPKG * 4)        // spk batch stride (bytes)

// One pipelined iteration covering BOTH batch elements:
// C(t-2), B(t-1), A(t) for b0 and b1; single barrier.
#define STEP(PA, XR0, XR1, DOA, DOB, DOC)                                      \
  {                                                                            \
    const int pa_ = (PA);                                                      \
    if ((DOC) && cTh) {                                                        \
      float c2a = part[0][pa_][0][ccol];                                       \
      float c2b = part[1][pa_][0][ccol];                                       \
      _Pragma("unroll")                                                        \
      for (int rr = 1; rr < 12; ++rr) {                                        \
        c2a += part[0][pa_][rr][ccol];                                         \
        c2b += part[1][pa_][rr][ccol];                                         \
      }                                                                        \
      c2a = __fadd_rn(c2a, bias2);                                             \
      c2b = __fadd_rn(c2b, bias2);                                             \
      float r2a = (mem2_0 > 1.0f) ? 1.0f : 0.0f;                               \
      float r2b = (mem2_1 > 1.0f) ? 1.0f : 0.0f;                               \
      mem2_0 = __fsub_rn(__fadd_rn(__fmul_rn(0.9f, mem2_0), c2a), r2a);        \
      mem2_1 = __fsub_rn(__fadd_rn(__fmul_rn(0.9f, mem2_1), c2b), r2b);        \
      acc0 += (double)mem2_0;                                                  \
      acc1 += (double)mem2_1;                                                  \
    }                                                                          \
    if ((DOB) && bTh) {                                                        \
      uint32_t sp0 = spkBbase + (uint32_t)((pa_ ^ 1) * PARSTR);                \
      uint32_t sp1 = sp0 + (uint32_t)BATSTR;                                   \
      ull a0 = 0ull, a1 = 0ull, b0 = 0ull, b1 = 0ull;                          \
      _Pragma("unroll")                                                        \
      for (int k = 0; k < 16; k += 2) {                                        \
        ull s0, s1, t0, t1;                                                    \
        asm("ld.shared.v2.u64 {%0,%1}, [%2];"                                  \
            : "=l"(s0), "=l"(s1) : "r"(sp0 + (uint32_t)(k * 8)));              \
        asm("ld.shared.v2.u64 {%0,%1}, [%2];"                                  \
            : "=l"(t0), "=l"(t1) : "r"(sp1 + (uint32_t)(k * 8)));              \
        a0 = f2fma(s0, w2[k],     a0);                                         \
        a1 = f2fma(s1, w2[k + 1], a1);                                         \
        b0 = f2fma(t0, w2[k],     b0);                                         \
        b1 = f2fma(t1, w2[k + 1], b1);                                         \
      }                                                                        \
      float x0_, x1_, y0_, y1_, u0_, u1_, v0_, v1_;                            \
      upk(a0, x0_, x1_); upk(a1, y0_, y1_);                                    \
      upk(b0, u0_, u1_); upk(b1, v0_, v1_);                                    \
      part[0][pa_ ^ 1][brow][bcol] = (x0_ + x1_) + (y0_ + y1_);                \
      part[1][pa_ ^ 1][brow][bcol] = (u0_ + u1_) + (v0_ + v1_);                \
    }                                                                          \
    if ((DOA) && aTh) {                                                        \
      const float* xr0 = (XR0) + pos;                                          \
      const float* xr1 = (XR1) + pos;                                          \
      float s0_ = __fmul_rn(xr0[0], wc[0]);                                    \
      float s1_ = __fmul_rn(xr1[0], wc[0]);                                    \
      _Pragma("unroll")                                                        \
      for (int k = 1; k < KW; ++k) {                                           \
        s0_ = __fmaf_rn(xr0[k], wc[k], s0_);                                   \
        s1_ = __fmaf_rn(xr1[k], wc[k], s1_);                                   \
      }                                                                        \
      float c10 = __fadd_rn(s0_, bc);                                          \
      float c11 = __fadd_rn(s1_, bc);                                          \
      float r10 = (mem1_0 > 1.0f) ? 1.0f : 0.0f;                               \
      float r11 = (mem1_1 > 1.0f) ? 1.0f : 0.0f;                               \
      mem1_0 = __fsub_rn(__fadd_rn(__fmul_rn(0.9f, mem1_0), c10), r10);        \
      mem1_1 = __fsub_rn(__fadd_rn(__fmul_rn(0.9f, mem1_1), c11), r11);        \
      spk[0][pa_][sIdx] = (mem1_0 > 1.0f) ? 1.0f : 0.0f;                       \
      spk[1][pa_][sIdx] = (mem1_1 > 1.0f) ? 1.0f : 0.0f;                       \
    }                                                                          \
    __syncthreads();                                                           \
  }

__global__ __launch_bounds__(NTHREADS, 1)
void snn_kernel(const float* __restrict__ x,
                const float* __restrict__ conv_w,
                const float* __restrict__ conv_b,
                const float* __restrict__ fc_w,
                const float* __restrict__ fc_b,
                float* __restrict__ out)
{
    __shared__ __align__(128) float xs[2][2][CHUNK * ROWP];  // [batch][buf] 25.6 KB
    __shared__ __align__(16)  float spk[2][2][12 * SPKG];    // [batch][parity]
    __shared__ __align__(16)  float part[2][2][12][PCOL];    // [batch][parity]

    const int b0   = 2 * blockIdx.x;
    const int b1   = b0 + 1;
    const int tid  = threadIdx.x;
    const int wid  = tid >> 5;
    const int lane = tid & 31;

    // ---- A state (warps 0-11): thread tid<384 owns j=tid (ch=j/24, pos=j%24), both batches ----
    const bool aTh = (wid < 12);
    const int  pos = tid % LO;
    const int  sIdx = wid * SPKG + lane;
    float wc[KW], bc = 0.f, mem1_0 = 0.f, mem1_1 = 0.f;
    if (aTh) {
        const int ch = tid / LO;
        #pragma unroll
        for (int k = 0; k < KW; ++k) wc[k] = conv_w[ch * KW + k];
        bc = conv_b[ch];
    }

    // ---- B state: warps 0-11 -> (r=wid, o=lane); threads 384-419 -> (r=i/3, o=32+i%3) ----
    bool bTh = false;
    int  brow = 0, bcol = 0;
    if (wid < 12)            { bTh = true; brow = wid;              bcol = lane; }
    else if (tid < 384 + 36) { bTh = true; int i = tid - 384; brow = i / 3; bcol = 32 + i % 3; }
    ull w2[16];
    if (bTh) {
        #pragma unroll
        for (int k = 0; k < 16; ++k)
            w2[k] = pk(fc_w[bcol * JDIM + brow * 32 + 2 * k],
                       fc_w[bcol * JDIM + brow * 32 + 2 * k + 1]);
    }
    const uint32_t spkBbase = smem_u32(&spk[0][0][0]) + (uint32_t)(brow * SPKG * 4);

    // ---- C state: warp 13 -> outputs 0-31; warp 12 lanes 29-31 -> outputs 32-34 ----
    bool cTh = false;
    int  ccol = 0;
    if (wid == 13)                    { cTh = true; ccol = lane; }
    else if (wid == 12 && lane >= 29) { cTh = true; ccol = 32 + (lane - 29); }
    float  bias2 = 0.f, mem2_0 = 0.f, mem2_1 = 0.f;
    double acc0 = 0.0, acc1 = 0.0;
    if (cTh) bias2 = fc_b[ccol];

    const float* xb0 = x + (size_t)b0 * TSTEPS * LIN;
    const float* xb1 = x + (size_t)b1 * TSTEPS * LIN;

    // ---- prefetch chunk 0: warp 12 copies batch0, warp 13 copies batch1 ----
    if (wid >= 12) {
        const int bat = wid - 12;
        const float* src = bat ? xb1 : xb0;
        uint32_t sbase = smem_u32(&xs[bat][0][0]);
        for (int i = lane; i < CHUNK * 15; i += 32) {
            int t = i / 15, c = i - t * 15;
            cp_async8(sbase + (uint32_t)(t * ROWP * 4 + c * 8), src + t * LIN + c * 2);
        }
    }
    cp_commit();

    for (int chunk = 0; chunk < NCHUNK; ++chunk) {
        const int buf = chunk & 1;
        if (chunk + 1 < NCHUNK) {
            if (wid >= 12) {
                const int bat = wid - 12;
                const float* src = (bat ? xb1 : xb0) + (size_t)(chunk + 1) * CHUNK * LIN;
                uint32_t sbase = smem_u32(&xs[bat][buf ^ 1][0]);
                for (int i = lane; i < CHUNK * 15; i += 32) {
                    int t = i / 15, c = i - t * 15;
                    cp_async8(sbase + (uint32_t)(t * ROWP * 4 + c * 8), src + t * LIN + c * 2);
                }
            }
            cp_commit();
            cp_wait1();
        } else {
            cp_wait0();
        }
        __syncthreads();

        const float* x0base = &xs[0][buf][0];
        const float* x1base = &xs[1][buf][0];
        if (chunk == 0) {
            #pragma unroll 2
            for (int tc = 0; tc < CHUNK; ++tc)
                STEP(tc & 1, x0base + tc * ROWP, x1base + tc * ROWP,
                     true, tc >= 1, tc >= 2);
        } else {
            #pragma unroll 2
            for (int tc = 0; tc < CHUNK; ++tc)
                STEP(tc & 1, x0base + tc * ROWP, x1base + tc * ROWP,
                     true, true, true);
        }
    }

    // ---- drain: t=1000 (B(999), C(998)); t=1001 (C(999)) ----
    STEP(0, &xs[0][0][0], &xs[1][0][0], false, true, true);
    STEP(1, &xs[0][0][0], &xs[1][0][0], false, false, true);

    if (cTh) {
        out[b0 * NOUT + ccol] = (float)(acc0 * (1.0 / (double)TSTEPS));
        out[b1 * NOUT + ccol] = (float)(acc1 * (1.0 / (double)TSTEPS));
    }
}

extern "C" void kernel_launch(void* const* d_in, const int* in_sizes, int n_in,
                              void* d_out, int out_size)
{
    const float* x      = (const float*)d_in[0];
    const float* conv_w = (const float*)d_in[1];
    const float* conv_b = (const float*)d_in[2];
    const float* fc_w   = (const float*)d_in[3];
    const float* fc_b   = (const float*)d_in[4];
    snn_kernel<<<BATCH / 2, NTHREADS>>>(x, conv_w, conv_b, fc_w, fc_b, (float*)d_out);
}

// round 12
// speedup vs baseline: 1.1606x; 1.1606x over previous
#include <cuda_runtime.h>
#include <cstdint>

#define BATCH   256
#define TSTEPS  1000
#define LIN     30
#define NCH     16
#define KW      7
#define LO      24
#define JDIM    384      // NCH*LO
#define NOUT    35
#define OPAD    36       // padded outputs
#define GR      12       // j-groups per output
#define JT      32       // j's per FC thread
#define NTHREADS 448     // warps 0-11: A+B | w12: B-extra + C | w13: B-extra tail
#define CHUNK   40       // timesteps per smem chunk (20 regions, even)
#define NCHUNK  (TSTEPS / CHUNK)
#define NREG    (CHUNK / 2)

typedef unsigned long long ull;

__device__ __forceinline__ uint32_t smem_u32(const void* p) {
    return (uint32_t)__cvta_generic_to_shared(p);
}
__device__ __forceinline__ void cp_async8(uint32_t dst, const void* src) {
    asm volatile("cp.async.ca.shared.global [%0], [%1], 8;" :: "r"(dst), "l"(src));
}
__device__ __forceinline__ void cp_commit() { asm volatile("cp.async.commit_group;"); }
__device__ __forceinline__ void cp_wait1()  { asm volatile("cp.async.wait_group 1;" ::: "memory"); }
__device__ __forceinline__ void cp_wait0()  { asm volatile("cp.async.wait_group 0;" ::: "memory"); }

__device__ __forceinline__ ull pk(float a, float b) {
    ull r; asm("mov.b64 %0, {%1,%2};" : "=l"(r) : "f"(a), "f"(b)); return r;
}
__device__ __forceinline__ void upk(ull v, float& a, float& b) {
    asm("mov.b64 {%0,%1}, %2;" : "=f"(a), "=f"(b) : "l"(v));
}
__device__ __forceinline__ ull f2fma(ull a, ull b, ull c) {
    ull d; asm("fma.rn.f32x2 %0, %1, %2, %3;" : "=l"(d) : "l"(a), "l"(b), "l"(c)); return d;
}

// ---- sub-phase helpers (arithmetic sequences verbatim from the 487us kernel) ----

#define DO_C_SUB(PBUF, SSUB)                                                   \
  {                                                                            \
    float c2 = part[PBUF][SSUB][0][cIdx];                                      \
    _Pragma("unroll")                                                          \
    for (int rr2 = 1; rr2 < GR; ++rr2) c2 += part[PBUF][SSUB][rr2][cIdx];      \
    c2 = __fadd_rn(c2, bias2);                                                 \
    float r2 = (mem2 > 1.0f) ? 1.0f : 0.0f;                                    \
    mem2 = __fsub_rn(__fadd_rn(__fmul_rn(0.9f, mem2), c2), r2);                \
    acc += (double)mem2;                                                       \
  }

#define DO_B_SUB(PBUF, SSUB)                                                   \
  {                                                                            \
    uint32_t sp = spkAddr + (uint32_t)((2 * (PBUF) + (SSUB)) * (JDIM * 4));    \
    ull a0 = 0ull, a1 = 0ull;                                                  \
    _Pragma("unroll")                                                          \
    for (int k = 0; k < JT / 2; k += 2) {                                      \
      ull s0, s1;                                                              \
      asm("ld.shared.v2.u64 {%0,%1}, [%2];"                                    \
          : "=l"(s0), "=l"(s1) : "r"(sp + (uint32_t)(k * 8)));                 \
      a0 = f2fma(s0, w2[k],     a0);                                           \
      a1 = f2fma(s1, w2[k + 1], a1);                                           \
    }                                                                          \
    float x0_, x1_, y0_, y1_;                                                  \
    upk(a0, x0_, x1_);                                                         \
    upk(a1, y0_, y1_);                                                         \
    part[(PBUF) ^ 1][SSUB][r][o] = (x0_ + x1_) + (y0_ + y1_);                  \
  }

#define DO_A_SUB(PBUF, SSUB, XROW)                                             \
  {                                                                            \
    const float* xr = (XROW) + pos;                                            \
    float s = __fmul_rn(xr[0], wc[0]);                                         \
    _Pragma("unroll")                                                          \
    for (int k = 1; k < KW; ++k) s = __fmaf_rn(xr[k], wc[k], s);               \
    float c1 = __fadd_rn(s, bc);                                               \
    float r1 = (mem1 > 1.0f) ? 1.0f : 0.0f;                                    \
    mem1 = __fsub_rn(__fadd_rn(__fmul_rn(0.9f, mem1), c1), r1);                \
    spk[PBUF][SSUB][tid] = (mem1 > 1.0f) ? 1.0f : 0.0f;                        \
  }

// One region = 2 timesteps: C(2R-4),C(2R-3); B(2R-2),B(2R-1); A(2R),A(2R+1).
// pr = R&1. A writes spk[pr][*]; B reads spk[pr^1][*], writes part[pr][*]
// (note DO_B_SUB takes the READ parity); C reads part[pr^1][*].
#define REGION(PR, XR0, XR1, DOA, DOB, DOC)                                    \
  {                                                                            \
    if ((DOC) && cTh) {                                                        \
      DO_C_SUB((PR) ^ 1, 0)                                                    \
      DO_C_SUB((PR) ^ 1, 1)                                                    \
    }                                                                          \
    if ((DOB) && fcth) {                                                       \
      DO_B_SUB((PR) ^ 1, 0)                                                    \
      DO_B_SUB((PR) ^ 1, 1)                                                    \
    }                                                                          \
    if ((DOA) && tid < JDIM) {                                                 \
      DO_A_SUB((PR), 0, XR0)                                                   \
      DO_A_SUB((PR), 1, XR1)                                                   \
    }                                                                          \
    __syncthreads();                                                           \
  }

__global__ __launch_bounds__(NTHREADS, 2)
void snn_kernel(const float* __restrict__ x,
                const float* __restrict__ conv_w,
                const float* __restrict__ conv_b,
                const float* __restrict__ fc_w,
                const float* __restrict__ fc_b,
                float* __restrict__ out)
{
    __shared__ __align__(16) float xs[2][CHUNK * LIN];    // 9.6 KB double-buffered x
    __shared__ __align__(16) float spk[2][2][JDIM];       // [parity][substep]
    __shared__ float part[2][2][GR][40];                  // [parity][substep]

    const int b   = blockIdx.x;
    const int tid = threadIdx.x;

    // ---- Phase A state: thread tid < 384 owns mem1[tid], tid = ch*24 + pos ----
    float wc[KW];
    float bc = 0.f, mem1 = 0.f;
    int pos = 0;
    if (tid < JDIM) {
        int ch = tid / LO;
        pos    = tid % LO;
        #pragma unroll
        for (int k = 0; k < KW; ++k) wc[k] = conv_w[ch * KW + k];
        bc = conv_b[ch];
    }

    // ---- Phase B state: threads 0-431 -> output o = tid%36, group r = tid/36 ----
    const bool fcth = (tid < GR * OPAD);
    const int  o    = tid % OPAD;
    const int  r    = tid / OPAD;
    ull w2[JT / 2];
    if (fcth) {
        #pragma unroll
        for (int k = 0; k < JT / 2; ++k) {
            float lo_ = 0.f, hi_ = 0.f;
            if (o < NOUT) {
                lo_ = fc_w[o * JDIM + r * JT + 2 * k];
                hi_ = fc_w[o * JDIM + r * JT + 2 * k + 1];
            }
            w2[k] = pk(lo_, hi_);
        }
    }
    const uint32_t spkAddr = smem_u32(&spk[0][0][r * JT]);

    // ---- Phase C state: threads 384..418 own output cIdx (warp 12) ----
    const bool cTh  = (tid >= JDIM) && (tid < JDIM + NOUT);
    const int  cIdx = tid - JDIM;
    float  bias2 = 0.f, mem2 = 0.f;
    double acc   = 0.0;
    if (cTh) bias2 = fc_b[cIdx];

    const float* xb = x + (size_t)b * TSTEPS * LIN;

    // ---- prefetch chunk 0 (1200 floats = 600 x 8B) ----
    {
        uint32_t sbase = smem_u32(&xs[0][0]);
        for (int i = tid; i < CHUNK * LIN / 2; i += NTHREADS)
            cp_async8(sbase + i * 8, xb + i * 2);
        cp_commit();
    }

    for (int chunk = 0; chunk < NCHUNK; ++chunk) {
        const int buf = chunk & 1;
        if (chunk + 1 < NCHUNK) {
            uint32_t sbase   = smem_u32(&xs[buf ^ 1][0]);
            const float* src = xb + (size_t)(chunk + 1) * CHUNK * LIN;
            for (int i = tid; i < CHUNK * LIN / 2; i += NTHREADS)
                cp_async8(sbase + i * 8, src + i * 2);
            cp_commit();
            cp_wait1();
        } else {
            cp_wait0();
        }
        __syncthreads();

        const float* xrow = &xs[buf][0];
        if (chunk == 0) {
            // fill: region 0 = A only; region 1 = A+B; region >=2 = all
            #pragma unroll 2
            for (int rr = 0; rr < NREG; ++rr)
                REGION(rr & 1, xrow + 2 * rr * LIN, xrow + (2 * rr + 1) * LIN,
                       true, rr >= 1, rr >= 2);
        } else {
            // steady state (NREG even -> region parity = rr&1 every chunk)
            #pragma unroll 2
            for (int rr = 0; rr < NREG; ++rr)
                REGION(rr & 1, xrow + 2 * rr * LIN, xrow + (2 * rr + 1) * LIN,
                       true, true, true);
        }
    }

    // ---- drain: region 500 (pr=0): B(998,999), C(996,997); region 501: C(998,999) ----
    REGION(0, (const float*)nullptr, (const float*)nullptr, false, true, true);
    REGION(1, (const float*)nullptr, (const float*)nullptr, false, false, true);

    if (cTh)
        out[b * NOUT + cIdx] = (float)(acc * (1.0 / (double)TSTEPS));
}

extern "C" void kernel_launch(void* const* d_in, const int* in_sizes, int n_in,
                              void* d_out, int out_size)
{
    const float* x      = (const float*)d_in[0];
    const float* conv_w = (const float*)d_in[1];
    const float* conv_b = (const float*)d_in[2];
    const float* fc_w   = (const float*)d_in[3];
    const float* fc_b   = (const float*)d_in[4];
    snn_kernel<<<BATCH, NTHREADS>>>(x, conv_w, conv_b, fc_w, fc_b, (float*)d_out);
}